// round 1
// baseline (speedup 1.0000x reference)
#include <cuda_runtime.h>
#include <math.h>

// ---------------------------------------------------------------------------
// QuantumSelfAttention — closed-form quantum scores
//
// score(i,j) = prod_{w=1..3} ( cos(th_w)*cos(q_iw) - sin(th_w)*sin(q_iw)*cos(k_jw) )
// (derived via Heisenberg conjugation of Z0 through the fixed circuit; theta_0 unused)
// ---------------------------------------------------------------------------

#define Bx 4
#define Sx 128
#define Dx 256
#define Hx 8
#define DKx 32

static __device__ float g_V[Bx*Sx*Dx];    // V = x@Wv.T + bv
static __device__ float g_AO[Bx*Sx*Dx];   // attention output (pre-Wo)
static __device__ float g_AB[Bx*Hx*Sx*6]; // per (b,h,i): A1,B1,A2,B2,A3,B3
static __device__ float g_CK[Bx*Hx*Sx*3]; // per (b,h,j): cos(k1),cos(k2),cos(k3)

// ---------------------------------------------------------------------------
// Kernel 1: Q/K features. Block = (b, group of 4 s-rows). 256 threads = 8 warps.
// Warp h computes 8 dot products (4 Wq rows + 4 Wk rows) x 4 s-rows, then
// normalizes to angles and emits trig features.
// ---------------------------------------------------------------------------
__global__ void __launch_bounds__(256) qk_feat(
    const float* __restrict__ x,
    const float* __restrict__ Wq, const float* __restrict__ bq,
    const float* __restrict__ Wk, const float* __restrict__ bk,
    const float* __restrict__ ap)
{
    __shared__ float xs[4][256];
    const int b  = blockIdx.x >> 5;     // 0..3
    const int sg = blockIdx.x & 31;     // 0..31
    const int s0 = sg << 2;
    const int tid = threadIdx.x;

    for (int t = tid; t < 1024; t += 256)
        xs[t >> 8][t & 255] = x[(b*Sx + s0 + (t >> 8))*Dx + (t & 255)];
    __syncthreads();

    const int h = tid >> 5, lane = tid & 31;
    float acc[4][8];
#pragma unroll
    for (int s = 0; s < 4; s++)
#pragma unroll
        for (int o = 0; o < 8; o++) acc[s][o] = 0.f;

    const float* wq = Wq + (h*DKx)*Dx;
    const float* wk = Wk + (h*DKx)*Dx;

#pragma unroll
    for (int c = 0; c < 8; c++) {
        const int d = lane + (c << 5);
        const float x0 = xs[0][d], x1 = xs[1][d], x2 = xs[2][d], x3 = xs[3][d];
#pragma unroll
        for (int o = 0; o < 4; o++) {
            const float wv = wq[o*Dx + d];
            acc[0][o] = fmaf(x0, wv, acc[0][o]);
            acc[1][o] = fmaf(x1, wv, acc[1][o]);
            acc[2][o] = fmaf(x2, wv, acc[2][o]);
            acc[3][o] = fmaf(x3, wv, acc[3][o]);
        }
#pragma unroll
        for (int o = 0; o < 4; o++) {
            const float wv = wk[o*Dx + d];
            acc[0][4+o] = fmaf(x0, wv, acc[0][4+o]);
            acc[1][4+o] = fmaf(x1, wv, acc[1][4+o]);
            acc[2][4+o] = fmaf(x2, wv, acc[2][4+o]);
            acc[3][4+o] = fmaf(x3, wv, acc[3][4+o]);
        }
    }

    // full butterfly: all lanes end up with complete sums
#pragma unroll
    for (int s = 0; s < 4; s++)
#pragma unroll
        for (int o = 0; o < 8; o++) {
            float v = acc[s][o];
            v += __shfl_xor_sync(0xffffffffu, v, 16);
            v += __shfl_xor_sync(0xffffffffu, v, 8);
            v += __shfl_xor_sync(0xffffffffu, v, 4);
            v += __shfl_xor_sync(0xffffffffu, v, 2);
            v += __shfl_xor_sync(0xffffffffu, v, 1);
            acc[s][o] = v;
        }

    if (lane < 8) {
        const int sp = lane >> 1;          // which s-row
        const int side = lane & 1;         // 0 = q, 1 = k
        const float* bias = side ? bk : bq;
        float vals[4];
#pragma unroll
        for (int w = 0; w < 4; w++)
            vals[w] = acc[sp][side*4 + w] + bias[h*DKx + w];

        const float mn = fminf(fminf(vals[0], vals[1]), fminf(vals[2], vals[3]));
        const float mx = fmaxf(fmaxf(vals[0], vals[1]), fmaxf(vals[2], vals[3]));
        const float sc = 3.14159265358979323846f / (mx - mn + 1e-8f);
        const int idx = (b*Hx + h)*Sx + s0 + sp;

        if (side == 0) {
#pragma unroll
            for (int w = 1; w < 4; w++) {
                const float ang = (vals[w] - mn) * sc;
                float sn, cs;
                sincosf(ang, &sn, &cs);
                const float th = ap[w];
                g_AB[idx*6 + (w-1)*2 + 0] = cosf(th) * cs;
                g_AB[idx*6 + (w-1)*2 + 1] = sinf(th) * sn;
            }
        } else {
#pragma unroll
            for (int w = 1; w < 4; w++)
                g_CK[idx*3 + (w-1)] = cosf((vals[w] - mn) * sc);
        }
    }
}

// ---------------------------------------------------------------------------
// Kernel 2/4: C[m][n] = sum_k A[m][k]*B[n][k] + bias[n]   (both row-major, K=256)
// 32x32 output tile per block, 128 threads, 2x4 micro-tile, XOR-swizzled
// float4 shared tiles for conflict-free LDS.128.
// mode 0: A = Ain, C = g_V     mode 1: A = g_AO, C = Cout
// ---------------------------------------------------------------------------
__global__ void __launch_bounds__(128) gemm_nt_bias(
    const float* Ain, const float* __restrict__ Bmat,
    const float* __restrict__ bias, float* Cout, int mode)
{
    const float* A = mode ? (const float*)g_AO : Ain;
    float*       C = mode ? Cout : (float*)g_V;

    __shared__ float4 As[1024];  // [32 m-rows][32 float4-cols], swizzled ^(r&7)
    __shared__ float4 Bs[1024];  // [32 n-rows][32 float4-cols], swizzled ^(r>>2)

    const float4* A4 = (const float4*)A;
    const float4* B4 = (const float4*)Bmat;

    const int m0 = blockIdx.y << 5;
    const int n0 = blockIdx.x << 5;
    const int tid = threadIdx.x;
    const int tx = tid & 7, ty = tid >> 3;   // tx: 0..7 (n), ty: 0..15 (m)
    const int mA = ty*2, mB = ty*2 + 1;
    const int swa0 = mA & 7, swa1 = mB & 7;
    const int nb = tx << 2;

    float acc[2][4];
#pragma unroll
    for (int mi = 0; mi < 2; mi++)
#pragma unroll
        for (int ni = 0; ni < 4; ni++) acc[mi][ni] = 0.f;

    for (int kc = 0; kc < 2; kc++) {
        for (int t = tid; t < 1024; t += 128) {
            const int r = t >> 5, c = t & 31;
            As[r*32 + (c ^ (r & 7))]          = A4[(m0 + r)*64 + (kc << 5) + c];
            Bs[r*32 + (c ^ ((r >> 2) & 7))]   = B4[(n0 + r)*64 + (kc << 5) + c];
        }
        __syncthreads();

#pragma unroll
        for (int c4 = 0; c4 < 32; c4++) {
            const float4 a0 = As[mA*32 + (c4 ^ swa0)];
            const float4 a1 = As[mB*32 + (c4 ^ swa1)];
#pragma unroll
            for (int ni = 0; ni < 4; ni++) {
                const float4 bv = Bs[(nb + ni)*32 + (c4 ^ tx)];
                acc[0][ni] = fmaf(a0.x, bv.x, acc[0][ni]);
                acc[0][ni] = fmaf(a0.y, bv.y, acc[0][ni]);
                acc[0][ni] = fmaf(a0.z, bv.z, acc[0][ni]);
                acc[0][ni] = fmaf(a0.w, bv.w, acc[0][ni]);
                acc[1][ni] = fmaf(a1.x, bv.x, acc[1][ni]);
                acc[1][ni] = fmaf(a1.y, bv.y, acc[1][ni]);
                acc[1][ni] = fmaf(a1.z, bv.z, acc[1][ni]);
                acc[1][ni] = fmaf(a1.w, bv.w, acc[1][ni]);
            }
        }
        __syncthreads();
    }

#pragma unroll
    for (int mi = 0; mi < 2; mi++)
#pragma unroll
        for (int ni = 0; ni < 4; ni++)
            C[(m0 + ty*2 + mi)*256 + n0 + nb + ni] = acc[mi][ni] + bias[n0 + nb + ni];
}

// ---------------------------------------------------------------------------
// Kernel 3: attention. Block = (b, h, quarter of i-rows), 128 threads.
// thread = (i_local = tid&31, p = tid>>5); p owns 8 output dims.
// Scores bounded in [-1,1] so no max-subtraction needed for softmax.
// ---------------------------------------------------------------------------
__global__ void __launch_bounds__(128) attn_kernel()
{
    const int iq = blockIdx.x & 3;
    const int bh = blockIdx.x >> 2;
    const int b = bh >> 3, h = bh & 7;

    __shared__ float  Vs[128][32];
    __shared__ float4 CKs[128];

    const int tid = threadIdx.x;
    const int il = tid & 31;
    const int p  = tid >> 5;

    for (int t = tid; t < 4096; t += 128) {
        const int j = t >> 5, d = t & 31;
        Vs[j][d] = g_V[(b*Sx + j)*Dx + h*DKx + d];
    }
    {
        const float* ck = &g_CK[(bh*Sx + tid)*3];
        CKs[tid] = make_float4(ck[0], ck[1], ck[2], 0.f);
    }
    __syncthreads();

    const int i = (iq << 5) + il;
    const float* ab = &g_AB[(bh*Sx + i)*6];
    const float A1 = ab[0], B1 = ab[1];
    const float A2 = ab[2], B2 = ab[3];
    const float A3 = ab[4], B3 = ab[5];

    const float SCALE = 0.17677669529663687f; // 1/sqrt(32)

    float l = 0.f;
    float o[8];
#pragma unroll
    for (int dd = 0; dd < 8; dd++) o[dd] = 0.f;

#pragma unroll 4
    for (int j = 0; j < 128; j++) {
        const float4 ck = CKs[j];
        const float s = (A1 - B1*ck.x) * (A2 - B2*ck.y) * (A3 - B3*ck.z);
        const float e = __expf(s * SCALE);
        l += e;
        const float* vr = &Vs[j][p << 3];
        const float4 v0 = *(const float4*)vr;
        const float4 v1 = *(const float4*)(vr + 4);
        o[0] = fmaf(e, v0.x, o[0]);
        o[1] = fmaf(e, v0.y, o[1]);
        o[2] = fmaf(e, v0.z, o[2]);
        o[3] = fmaf(e, v0.w, o[3]);
        o[4] = fmaf(e, v1.x, o[4]);
        o[5] = fmaf(e, v1.y, o[5]);
        o[6] = fmaf(e, v1.z, o[6]);
        o[7] = fmaf(e, v1.w, o[7]);
    }

    const float inv = 1.0f / l;
    const int base = (b*Sx + i)*Dx + h*DKx + (p << 3);
#pragma unroll
    for (int dd = 0; dd < 8; dd++)
        g_AO[base + dd] = o[dd] * inv;
}

// ---------------------------------------------------------------------------
extern "C" void kernel_launch(void* const* d_in, const int* in_sizes, int n_in,
                              void* d_out, int out_size)
{
    const float* x  = (const float*)d_in[0];
    const float* Wq = (const float*)d_in[1];
    const float* bq = (const float*)d_in[2];
    const float* Wk = (const float*)d_in[3];
    const float* bk = (const float*)d_in[4];
    const float* Wv = (const float*)d_in[5];
    const float* bv = (const float*)d_in[6];
    const float* Wo = (const float*)d_in[7];
    const float* bo = (const float*)d_in[8];
    const float* ap = (const float*)d_in[9];
    float* out = (float*)d_out;

    // 1) Q/K angle features (independent of 2)
    qk_feat<<<128, 256>>>(x, Wq, bq, Wk, bk, ap);

    // 2) V = x @ Wv.T + bv  -> g_V
    gemm_nt_bias<<<dim3(8, 16), 128>>>(x, Wv, bv, nullptr, 0);

    // 3) attention -> g_AO
    attn_kernel<<<128, 128>>>();

    // 4) out = g_AO @ Wo.T + bo -> d_out
    gemm_nt_bias<<<dim3(8, 16), 128>>>(nullptr, Wo, bo, out, 1);
}

// round 2
// speedup vs baseline: 1.4431x; 1.4431x over previous
#include <cuda_runtime.h>
#include <math.h>

#define Bx 4
#define Sx 128
#define Dx 256
#define Hx 8

static __device__ float  g_V [Bx*Sx*Dx];     // V = x@Wv.T + bv
static __device__ float  g_AO[Bx*Sx*Dx];     // attention output (pre-Wo)
static __device__ float  g_AB[Bx*Hx*Sx*6];   // per (b,h,i): A1,B1,A2,B2,A3,B3
static __device__ float4 g_CK[Bx*Hx*Sx];     // per (b,h,j): cos(k1..k3), pad

// ---------------------------------------------------------------------------
// GEMM tile core: C[m0+m][n0+n] = sum_k A[m][k]*B[n][k] + bias[n], K=256.
// 256 threads = 8 warps. Warp w: n-half h=w&1 (16 n), k-quarter q=w>>1 (64 k).
// lane = m row. A via swizzled LDS.128, B via smem broadcast (crossbar-free).
// Each warp issues 1024 FFMA -> 2 warps/SMSP saturate the FFMA pipe (rt=2).
// k-partials reduced through smem (17-padded, aliased over dead tiles).
// ---------------------------------------------------------------------------
__device__ __forceinline__ void gemm_tile(
    const float4* __restrict__ A4, const float4* __restrict__ B4,
    const float* __restrict__ bias, float* __restrict__ C,
    int m0, int n0, float4* tiles /* 2048 float4 = 32KB */)
{
    float4* As = tiles;         // [32 m][32 k4], col swizzled ^(m&7)
    float4* Bs = tiles + 1024;  // [32 n][32 k4], col swizzled ^(n&7)
    const int tid  = threadIdx.x;
    const int lane = tid & 31;
    const int w    = tid >> 5;
    const int h    = w & 1;
    const int q    = w >> 1;

    float acc[16];
#pragma unroll
    for (int n = 0; n < 16; n++) acc[n] = 0.f;

    for (int kc = 0; kc < 2; kc++) {
#pragma unroll
        for (int r = 0; r < 4; r++) {
            const int m = w + (r << 3);                 // 0..31
            const int sc = lane ^ (m & 7);
            As[m*32 + sc] = A4[(m0 + m)*64 + (kc << 5) + lane];
            Bs[m*32 + sc] = B4[(n0 + m)*64 + (kc << 5) + lane];
        }
        __syncthreads();
#pragma unroll
        for (int kk = 0; kk < 8; kk++) {
            const int k4 = (q << 3) + kk;
            const float4 a = As[lane*32 + (k4 ^ (lane & 7))];
#pragma unroll
            for (int n = 0; n < 16; n++) {
                const int nn = (h << 4) + n;            // nn&7 == n&7
                const float4 b = Bs[nn*32 + (k4 ^ (n & 7))];
                acc[n] = fmaf(a.x, b.x, acc[n]);
                acc[n] = fmaf(a.y, b.y, acc[n]);
                acc[n] = fmaf(a.z, b.z, acc[n]);
                acc[n] = fmaf(a.w, b.w, acc[n]);
            }
        }
        __syncthreads();
    }

    // reduce 4 k-partials through smem (alias over tiles; 8*32*17*4B = 17.4KB)
    float* red = (float*)tiles;
#pragma unroll
    for (int n = 0; n < 16; n++)
        red[((q*2 + h)*32 + lane)*17 + n] = acc[n];
    __syncthreads();

    const int n  = tid & 31;
    const int mg = tid >> 5;
    const int hh = n >> 4, nl = n & 15;
#pragma unroll
    for (int r = 0; r < 4; r++) {
        const int m = mg*4 + r;
        float s = red[((0 + hh)*32 + m)*17 + nl]
                + red[((2 + hh)*32 + m)*17 + nl]
                + red[((4 + hh)*32 + m)*17 + nl]
                + red[((6 + hh)*32 + m)*17 + nl];
        C[(m0 + m)*256 + n0 + n] = s + bias[n0 + n];
    }
}

// ---------------------------------------------------------------------------
// Q/K features (device body). Block = (b, 4 s-rows), 256 threads = 8 warps.
// score(i,j) = prod_{w=1..3}( cos(th_w)cos(q_iw) - sin(th_w)sin(q_iw)cos(k_jw) )
// ---------------------------------------------------------------------------
__device__ void feat_body(
    const float* __restrict__ x,
    const float* __restrict__ Wq, const float* __restrict__ bq,
    const float* __restrict__ Wk, const float* __restrict__ bk,
    const float* __restrict__ ap, int bid, float* smem)
{
    float (*xs)[256] = (float(*)[256])smem;
    const int b  = bid >> 5;
    const int s0 = (bid & 31) << 2;
    const int tid = threadIdx.x;

    for (int t = tid; t < 1024; t += 256)
        xs[t >> 8][t & 255] = x[(b*Sx + s0 + (t >> 8))*Dx + (t & 255)];
    __syncthreads();

    const int h = tid >> 5, lane = tid & 31;
    float acc[4][8];
#pragma unroll
    for (int s = 0; s < 4; s++)
#pragma unroll
        for (int o = 0; o < 8; o++) acc[s][o] = 0.f;

    const float* wq = Wq + (h*32)*Dx;
    const float* wk = Wk + (h*32)*Dx;

#pragma unroll
    for (int c = 0; c < 8; c++) {
        const int d = lane + (c << 5);
        const float x0 = xs[0][d], x1 = xs[1][d], x2 = xs[2][d], x3 = xs[3][d];
#pragma unroll
        for (int o = 0; o < 4; o++) {
            const float wv = wq[o*Dx + d];
            acc[0][o] = fmaf(x0, wv, acc[0][o]);
            acc[1][o] = fmaf(x1, wv, acc[1][o]);
            acc[2][o] = fmaf(x2, wv, acc[2][o]);
            acc[3][o] = fmaf(x3, wv, acc[3][o]);
        }
#pragma unroll
        for (int o = 0; o < 4; o++) {
            const float wv = wk[o*Dx + d];
            acc[0][4+o] = fmaf(x0, wv, acc[0][4+o]);
            acc[1][4+o] = fmaf(x1, wv, acc[1][4+o]);
            acc[2][4+o] = fmaf(x2, wv, acc[2][4+o]);
            acc[3][4+o] = fmaf(x3, wv, acc[3][4+o]);
        }
    }

#pragma unroll
    for (int s = 0; s < 4; s++)
#pragma unroll
        for (int o = 0; o < 8; o++) {
            float v = acc[s][o];
            v += __shfl_xor_sync(0xffffffffu, v, 16);
            v += __shfl_xor_sync(0xffffffffu, v, 8);
            v += __shfl_xor_sync(0xffffffffu, v, 4);
            v += __shfl_xor_sync(0xffffffffu, v, 2);
            v += __shfl_xor_sync(0xffffffffu, v, 1);
            acc[s][o] = v;
        }

    if (lane < 8) {
        const int sp = lane >> 1;
        const int side = lane & 1;
        const float* bias = side ? bk : bq;
        float vals[4];
#pragma unroll
        for (int wv = 0; wv < 4; wv++)
            vals[wv] = acc[sp][side*4 + wv] + bias[h*32 + wv];

        const float mn = fminf(fminf(vals[0], vals[1]), fminf(vals[2], vals[3]));
        const float mx = fmaxf(fmaxf(vals[0], vals[1]), fmaxf(vals[2], vals[3]));
        const float sc = 3.14159265358979323846f / (mx - mn + 1e-8f);
        const int idx = (b*Hx + h)*Sx + s0 + sp;

        if (side == 0) {
#pragma unroll
            for (int wv = 1; wv < 4; wv++) {
                const float ang = (vals[wv] - mn) * sc;
                float sn, cs;
                sincosf(ang, &sn, &cs);
                const float th = ap[wv];
                g_AB[idx*6 + (wv-1)*2 + 0] = cosf(th) * cs;
                g_AB[idx*6 + (wv-1)*2 + 1] = sinf(th) * sn;
            }
        } else {
            float c1 = cosf((vals[1] - mn) * sc);
            float c2 = cosf((vals[2] - mn) * sc);
            float c3 = cosf((vals[3] - mn) * sc);
            g_CK[idx] = make_float4(c1, c2, c3, 0.f);
        }
    }
}

// ---------------------------------------------------------------------------
// Kernel 1: fused qk_feat + V-GEMM (independent work, one launch)
// ---------------------------------------------------------------------------
__global__ void __launch_bounds__(256) fused_feat_vgemm(
    const float* __restrict__ x,
    const float* __restrict__ Wq, const float* __restrict__ bq,
    const float* __restrict__ Wk, const float* __restrict__ bk,
    const float* __restrict__ ap,
    const float* __restrict__ Wv, const float* __restrict__ bv)
{
    __shared__ float4 tiles[2048];
    if (blockIdx.x < 128) {
        gemm_tile((const float4*)x, (const float4*)Wv, bv, g_V,
                  (blockIdx.x >> 3) << 5, (blockIdx.x & 7) << 5, tiles);
    } else {
        feat_body(x, Wq, bq, Wk, bk, ap, blockIdx.x - 128, (float*)tiles);
    }
}

// ---------------------------------------------------------------------------
// Kernel 2: attention. 256 blocks = (b,h, i-sixteenth of 16 rows), 128 thr.
// thread = (il = tid&15, p = tid>>4 owning 4 dims). Scores in [-1,1]*0.177
// -> single-pass softmax, no max subtraction.
// ---------------------------------------------------------------------------
__global__ void __launch_bounds__(128) attn_kernel()
{
    const int bx = blockIdx.x;
    const int ie = bx & 7;
    const int bh = bx >> 3;
    const int b = bh >> 3, h5 = bh & 7;

    __shared__ float4 Vs[128*8];   // [j][d4]
    __shared__ float4 CKs[128];

    const int tid = threadIdx.x;
    const float4* V4 = (const float4*)g_V;
#pragma unroll
    for (int r = 0; r < 8; r++) {
        const int idx = tid + (r << 7);       // idx = j*8 + d4
        const int j = idx >> 3, d4 = idx & 7;
        Vs[idx] = V4[(b*Sx + j)*64 + h5*8 + d4];
    }
    CKs[tid] = g_CK[bh*Sx + tid];
    if (tid < 0) __syncthreads();   // (placeholder removed below)
    __syncthreads();

    const int il = tid & 15, p = tid >> 4;
    const int i = ie*16 + il;
    const float* ab = &g_AB[(bh*Sx + i)*6];
    const float A1 = ab[0], B1 = ab[1];
    const float A2 = ab[2], B2 = ab[3];
    const float A3 = ab[4], B3 = ab[5];
    const float SCALE = 0.17677669529663687f; // 1/sqrt(32)

    float l = 0.f;
    float4 o = make_float4(0.f, 0.f, 0.f, 0.f);

#pragma unroll 8
    for (int j = 0; j < 128; j++) {
        const float4 ck = CKs[j];
        const float s = (A1 - B1*ck.x) * (A2 - B2*ck.y) * (A3 - B3*ck.z);
        const float e = __expf(s * SCALE);
        l += e;
        const float4 v = Vs[j*8 + p];
        o.x = fmaf(e, v.x, o.x);
        o.y = fmaf(e, v.y, o.y);
        o.z = fmaf(e, v.z, o.z);
        o.w = fmaf(e, v.w, o.w);
    }

    const float inv = 1.0f / l;
    o.x *= inv; o.y *= inv; o.z *= inv; o.w *= inv;
    ((float4*)g_AO)[(b*Sx + i)*64 + h5*8 + p] = o;
}

// ---------------------------------------------------------------------------
// Kernel 3: out = g_AO @ Wo.T + bo
// ---------------------------------------------------------------------------
__global__ void __launch_bounds__(256) gemm_out(
    const float* __restrict__ Wo, const float* __restrict__ bo,
    float* __restrict__ out)
{
    __shared__ float4 tiles[2048];
    gemm_tile((const float4*)g_AO, (const float4*)Wo, bo, out,
              (blockIdx.x >> 3) << 5, (blockIdx.x & 7) << 5, tiles);
}

// ---------------------------------------------------------------------------
extern "C" void kernel_launch(void* const* d_in, const int* in_sizes, int n_in,
                              void* d_out, int out_size)
{
    const float* x  = (const float*)d_in[0];
    const float* Wq = (const float*)d_in[1];
    const float* bq = (const float*)d_in[2];
    const float* Wk = (const float*)d_in[3];
    const float* bk = (const float*)d_in[4];
    const float* Wv = (const float*)d_in[5];
    const float* bv = (const float*)d_in[6];
    const float* Wo = (const float*)d_in[7];
    const float* bo = (const float*)d_in[8];
    const float* ap = (const float*)d_in[9];
    float* out = (float*)d_out;

    fused_feat_vgemm<<<256, 256>>>(x, Wq, bq, Wk, bk, ap, Wv, bv);
    attn_kernel<<<256, 128>>>();
    gemm_out<<<128, 256>>>(Wo, bo, out);
}